// round 14
// baseline (speedup 1.0000x reference)
#include <cuda_runtime.h>
#include <cuda_bf16.h>
#include <math.h>

#define NB 4
#define NTOK 2048
#define NATOMS 16384
#define CATOM 128
#define CTOK 384
#define NQ 32
#define NKEY 128
#define NHEADS 4
#define NWIN (NATOMS / NQ)   // 512
#define PAD 48

// ---------------- scratch (static device globals; no allocation) -------------
__device__ float g_x[NB * NATOMS * CATOM];
__device__ float g_h[NB * NATOMS * CATOM];
__device__ float g_qkv[NB * NATOMS * 384];
__device__ float g_o[NB * NATOMS * CATOM];
__device__ float g_hid[NB * NATOMS * 512];
__device__ float g_atok[NB * NTOK * CATOM];
__device__ float g_bias[NB * NHEADS * NQ * NKEY];

// packed bf16 hi/lo weight buffers: layout [N][K/2] words per matrix
__device__ unsigned g_wqkv_h[3 * 384 * 64],  g_wqkv_l[3 * 384 * 64];
__device__ unsigned g_wo_h[3 * 128 * 64],    g_wo_l[3 * 128 * 64];
__device__ unsigned g_wt1_h[3 * 512 * 64],   g_wt1_l[3 * 512 * 64];
__device__ unsigned g_wt2_h[3 * 128 * 256],  g_wt2_l[3 * 128 * 256];
__device__ unsigned g_wa_h[128 * 192],       g_wa_l[128 * 192];
__device__ unsigned g_wout_h[128 * 64],      g_wout_l[128 * 64];

// ---------------- helpers ----------------------------------------------------
__device__ __forceinline__ void mma_bf16(float* c, const unsigned* a, const unsigned* b) {
    asm volatile(
        "mma.sync.aligned.m16n8k16.row.col.f32.bf16.bf16.f32 "
        "{%0,%1,%2,%3}, {%4,%5,%6,%7}, {%8,%9}, {%0,%1,%2,%3};"
        : "+f"(c[0]), "+f"(c[1]), "+f"(c[2]), "+f"(c[3])
        : "r"(a[0]), "r"(a[1]), "r"(a[2]), "r"(a[3]), "r"(b[0]), "r"(b[1]));
}
__device__ __forceinline__ void ldsm_x4(unsigned& r0, unsigned& r1, unsigned& r2,
                                        unsigned& r3, unsigned addr) {
    asm volatile("ldmatrix.sync.aligned.m8n8.x4.shared.b16 {%0,%1,%2,%3}, [%4];"
                 : "=r"(r0), "=r"(r1), "=r"(r2), "=r"(r3) : "r"(addr));
}
__device__ __forceinline__ void pack2(float f0, float f1, unsigned& hi, unsigned& lo) {
    unsigned short h0 = __bfloat16_as_ushort(__float2bfloat16(f0));
    unsigned short h1 = __bfloat16_as_ushort(__float2bfloat16(f1));
    float r0 = f0 - __bfloat162float(__ushort_as_bfloat16(h0));
    float r1 = f1 - __bfloat162float(__ushort_as_bfloat16(h1));
    unsigned short l0 = __bfloat16_as_ushort(__float2bfloat16(r0));
    unsigned short l1 = __bfloat16_as_ushort(__float2bfloat16(r1));
    hi = (unsigned)h0 | ((unsigned)h1 << 16);
    lo = (unsigned)l0 | ((unsigned)l1 << 16);
}
__device__ __forceinline__ void pack_w_elem(const float* W, int K, int N, int e,
                                            unsigned* hi, unsigned* lo) {
    int Kw = K >> 1;
    int m = e / (N * Kw);
    int rem = e - m * N * Kw;
    int n = rem / Kw, kw = rem - n * Kw;
    const float* Wm = W + (size_t)m * K * N;
    pack2(Wm[(size_t)(2 * kw) * N + n], Wm[(size_t)(2 * kw + 1) * N + n], hi[e], lo[e]);
}

// ---------------- single weight-pack kernel ----------------------------------
#define S0 73728
#define S1 (S0 + 24576)
#define S2 (S1 + 98304)
#define S3 (S2 + 98304)
#define S4 (S3 + 24576)
#define S5 (S4 + 8192)
__global__ void pack_all(const float* __restrict__ Wq, const float* __restrict__ Wk,
                         const float* __restrict__ Wv, const float* __restrict__ Wo,
                         const float* __restrict__ Wt1, const float* __restrict__ Wt2,
                         const float* __restrict__ W_a, const float* __restrict__ W_out,
                         unsigned* qkv_h, unsigned* qkv_l, unsigned* wo_h, unsigned* wo_l,
                         unsigned* wt1_h, unsigned* wt1_l, unsigned* wt2_h, unsigned* wt2_l,
                         unsigned* wa_h, unsigned* wa_l, unsigned* wout_h, unsigned* wout_l) {
    int e = blockIdx.x * blockDim.x + threadIdx.x;
    if (e < S0) {
        int l = e / (384 * 64);
        int rem = e - l * (384 * 64);
        int n = rem >> 6, kw = rem & 63;
        const float* src = ((n < 128) ? Wq : (n < 256) ? Wk : Wv) + (size_t)l * 128 * 128;
        int nn = n & 127;
        pack2(src[(size_t)(2 * kw) * 128 + nn], src[(size_t)(2 * kw + 1) * 128 + nn],
              qkv_h[e], qkv_l[e]);
    } else if (e < S1) pack_w_elem(Wo, 128, 128, e - S0, wo_h, wo_l);
    else if (e < S2) pack_w_elem(Wt1, 128, 512, e - S1, wt1_h, wt1_l);
    else if (e < S3) pack_w_elem(Wt2, 512, 128, e - S2, wt2_h, wt2_l);
    else if (e < S4) pack_w_elem(W_a, 384, 128, e - S3, wa_h, wa_l);
    else if (e < S5) pack_w_elem(W_out, 128, 128, e - S4, wout_h, wout_l);
}

// ---------------- 3xBF16 GEMM, templated on BM x BN tile ---------------------
// flags: bit0=relu, bit1=add Cin, bit2=fused LN->H (needs TBN=128, grid.x=1, Cin)
template <int TBM, int TBN>
__global__ void __launch_bounds__(256)
gemm_bf3p(const float* __restrict__ A, const unsigned* __restrict__ Bhi,
          const unsigned* __restrict__ Blo, const float* __restrict__ Cin,
          float* __restrict__ C, int M, int N, int K, int flags,
          const float* __restrict__ LNg, const float* __restrict__ LNb,
          float* __restrict__ H) {
    constexpr int NWN = TBN / 32;          // warps along n
    constexpr int NWM = 8 / NWN;           // warps along m
    constexpr int MI = TBM / (16 * NWM);   // 16-row m-tiles per warp
    constexpr int TPRA = 256 / TBM;        // threads per A row
    constexpr int AWPT = 16 / TPRA;        // packed words per thread (A)
    __shared__ unsigned Ah[TBM][20], Al[TBM][20];
    __shared__ unsigned Bh[TBN][20], Bl[TBN][20];
    int tid = threadIdx.x;
    int wid = tid >> 5, lane = tid & 31;
    int wm = wid / NWN, wn = wid % NWN;
    int g = lane >> 2, tg = lane & 3;
    const float* Ag = A + (size_t)blockIdx.y * TBM * K;
    int Kw = K >> 1;
    const unsigned* Bgh = Bhi + (size_t)blockIdx.x * TBN * Kw;
    const unsigned* Bgl = Blo + (size_t)blockIdx.x * TBN * Kw;
    float c[MI][4][4] = {};

    int lrow = lane & 15;
    int lph = (lane >> 4) * 4;
    unsigned aHb = (unsigned)__cvta_generic_to_shared(&Ah[0][0]);
    unsigned aLb = (unsigned)__cvta_generic_to_shared(&Al[0][0]);
    unsigned bHb = (unsigned)__cvta_generic_to_shared(&Bh[0][0]);
    unsigned bLb = (unsigned)__cvta_generic_to_shared(&Bl[0][0]);

    int arow = tid / TPRA, aw = (tid % TPRA) * AWPT;
    int brow, bwd;
    if (TBN == 128) { brow = tid >> 1; bwd = (tid & 1) * 8; }
    else            { brow = tid >> 2; bwd = (tid & 3) * 4; }
    float4 ra[AWPT / 2];
    uint4 rbh0, rbh1, rbl0, rbl1;

#pragma unroll
    for (int i = 0; i < AWPT / 2; i++)
        ra[i] = *(const float4*)(Ag + (size_t)arow * K + aw * 2 + 4 * i);
    rbh0 = *(const uint4*)(Bgh + (size_t)brow * Kw + bwd);
    rbl0 = *(const uint4*)(Bgl + (size_t)brow * Kw + bwd);
    if (TBN == 128) {
        rbh1 = *(const uint4*)(Bgh + (size_t)brow * Kw + bwd + 4);
        rbl1 = *(const uint4*)(Bgl + (size_t)brow * Kw + bwd + 4);
    }

    int tiles = K / 32;
    for (int t = 0; t < tiles; t++) {
        {
            unsigned wh[AWPT], wl[AWPT];
#pragma unroll
            for (int i = 0; i < AWPT / 2; i++) {
                pack2(ra[i].x, ra[i].y, wh[2 * i], wl[2 * i]);
                pack2(ra[i].z, ra[i].w, wh[2 * i + 1], wl[2 * i + 1]);
            }
#pragma unroll
            for (int u = 0; u < AWPT / 4; u++) {
                *(uint4*)&Ah[arow][aw + 4 * u] =
                    make_uint4(wh[4 * u], wh[4 * u + 1], wh[4 * u + 2], wh[4 * u + 3]);
                *(uint4*)&Al[arow][aw + 4 * u] =
                    make_uint4(wl[4 * u], wl[4 * u + 1], wl[4 * u + 2], wl[4 * u + 3]);
            }
            *(uint4*)&Bh[brow][bwd] = rbh0;
            *(uint4*)&Bl[brow][bwd] = rbl0;
            if (TBN == 128) {
                *(uint4*)&Bh[brow][bwd + 4] = rbh1;
                *(uint4*)&Bl[brow][bwd + 4] = rbl1;
            }
        }
        __syncthreads();
        if (t + 1 < tiles) {
            int kt = (t + 1) * 32;
#pragma unroll
            for (int i = 0; i < AWPT / 2; i++)
                ra[i] = *(const float4*)(Ag + (size_t)arow * K + kt + aw * 2 + 4 * i);
            int ktw = kt >> 1;
            rbh0 = *(const uint4*)(Bgh + (size_t)brow * Kw + ktw + bwd);
            rbl0 = *(const uint4*)(Bgl + (size_t)brow * Kw + ktw + bwd);
            if (TBN == 128) {
                rbh1 = *(const uint4*)(Bgh + (size_t)brow * Kw + ktw + bwd + 4);
                rbl1 = *(const uint4*)(Bgl + (size_t)brow * Kw + ktw + bwd + 4);
            }
        }
#pragma unroll
        for (int ks2 = 0; ks2 < 2; ks2++) {
            int kc = ks2 * 8 + lph;
            unsigned ah[MI][4], al[MI][4], bhf[2][4], blf[2][4];
#pragma unroll
            for (int i = 0; i < MI; i++) {
                unsigned off = (unsigned)(((wm * 16 * MI + i * 16 + lrow) * 20 + kc) * 4);
                ldsm_x4(ah[i][0], ah[i][1], ah[i][2], ah[i][3], aHb + off);
                ldsm_x4(al[i][0], al[i][1], al[i][2], al[i][3], aLb + off);
            }
#pragma unroll
            for (int jp = 0; jp < 2; jp++) {
                unsigned off = (unsigned)(((wn * 32 + jp * 16 + lrow) * 20 + kc) * 4);
                ldsm_x4(bhf[jp][0], bhf[jp][1], bhf[jp][2], bhf[jp][3], bHb + off);
                ldsm_x4(blf[jp][0], blf[jp][1], blf[jp][2], blf[jp][3], bLb + off);
            }
#pragma unroll
            for (int i = 0; i < MI; i++)
#pragma unroll
                for (int j = 0; j < 4; j++) {
                    unsigned bh2[2] = {bhf[j >> 1][j & 1], bhf[j >> 1][(j & 1) + 2]};
                    unsigned bl2[2] = {blf[j >> 1][j & 1], blf[j >> 1][(j & 1) + 2]};
                    mma_bf16(c[i][j], ah[i], bl2);
                    mma_bf16(c[i][j], al[i], bh2);
                    mma_bf16(c[i][j], ah[i], bh2);
                }
        }
        __syncthreads();
    }

    if (TBN == 128) {
        if (flags & 4) {
            float* rsum = (float*)&Ah[0][0];    // [TBM][4]
            float* rsq  = (float*)&Al[0][0];
            float* gln  = (float*)&Bh[0][0];
            float* bln  = gln + 128;
            if (tid < 128) gln[tid] = LNg[tid];
            else if (tid < 256) bln[tid - 128] = LNb[tid - 128];
#pragma unroll
            for (int i = 0; i < MI; i++) {
#pragma unroll
                for (int hf = 0; hf < 2; hf++) {
                    int r = wm * 16 * MI + i * 16 + g + hf * 8;
                    float ps = 0.f, pq = 0.f;
#pragma unroll
                    for (int j = 0; j < 4; j++) {
                        int tt = hf * 2;
                        size_t idx = (size_t)(blockIdx.y * TBM + r) * 128 + wn * 32 + j * 8 + 2 * tg;
                        float2 p = *(const float2*)(Cin + idx);
                        float v0 = c[i][j][tt] + p.x;
                        float v1 = c[i][j][tt + 1] + p.y;
                        c[i][j][tt] = v0; c[i][j][tt + 1] = v1;
                        ps += v0 + v1; pq += v0 * v0 + v1 * v1;
                    }
                    ps += __shfl_xor_sync(0xffffffff, ps, 1);
                    ps += __shfl_xor_sync(0xffffffff, ps, 2);
                    pq += __shfl_xor_sync(0xffffffff, pq, 1);
                    pq += __shfl_xor_sync(0xffffffff, pq, 2);
                    if (tg == 0) { rsum[r * 4 + wn] = ps; rsq[r * 4 + wn] = pq; }
                }
            }
            __syncthreads();
#pragma unroll
            for (int i = 0; i < MI; i++) {
#pragma unroll
                for (int hf = 0; hf < 2; hf++) {
                    int r = wm * 16 * MI + i * 16 + g + hf * 8;
                    float4 s4 = *(float4*)&rsum[r * 4];
                    float4 q4 = *(float4*)&rsq[r * 4];
                    float mean = (s4.x + s4.y + s4.z + s4.w) * (1.f / 128.f);
                    float var = (q4.x + q4.y + q4.z + q4.w) * (1.f / 128.f) - mean * mean;
                    float rstd = rsqrtf(var + 1e-5f);
                    size_t rowoff = (size_t)(blockIdx.y * TBM + r) * 128;
#pragma unroll
                    for (int j = 0; j < 4; j++) {
                        int tt = hf * 2;
                        int col = wn * 32 + j * 8 + 2 * tg;
                        float v0 = c[i][j][tt], v1 = c[i][j][tt + 1];
                        *(float2*)(C + rowoff + col) = make_float2(v0, v1);
                        float h0 = (v0 - mean) * rstd * gln[col] + bln[col];
                        float h1 = (v1 - mean) * rstd * gln[col + 1] + bln[col + 1];
                        *(float2*)(H + rowoff + col) = make_float2(h0, h1);
                    }
                }
            }
            return;
        }
    }

#pragma unroll
    for (int i = 0; i < MI; i++) {
        int r0 = blockIdx.y * TBM + wm * 16 * MI + i * 16 + g;
#pragma unroll
        for (int j = 0; j < 4; j++) {
            int c0 = blockIdx.x * TBN + wn * 32 + j * 8 + 2 * tg;
            float2 v0 = make_float2(c[i][j][0], c[i][j][1]);
            float2 v1 = make_float2(c[i][j][2], c[i][j][3]);
            if (flags & 1) {
                v0.x = fmaxf(v0.x, 0.f); v0.y = fmaxf(v0.y, 0.f);
                v1.x = fmaxf(v1.x, 0.f); v1.y = fmaxf(v1.y, 0.f);
            }
            size_t i0 = (size_t)r0 * N + c0;
            size_t i1 = (size_t)(r0 + 8) * N + c0;
            if (flags & 2) {
                float2 p0 = *(const float2*)(Cin + i0);
                float2 p1 = *(const float2*)(Cin + i1);
                v0.x += p0.x; v0.y += p0.y;
                v1.x += p1.x; v1.y += p1.y;
            }
            *(float2*)(C + i0) = v0;
            *(float2*)(C + i1) = v1;
        }
    }
}

// ---------------- gather token features to atoms (float4) --------------------
__global__ void gather_kernel(const float* __restrict__ atok, const int* __restrict__ idx,
                              float* __restrict__ x) {
    size_t i = (size_t)blockIdx.x * blockDim.x + threadIdx.x;
    if (i >= (size_t)NB * NATOMS * 32) return;
    int c4 = (int)(i & 31);
    size_t n = i >> 5;
    int b = (int)(n >> 14);
    int atom = (int)(n & (NATOMS - 1));
    int tok = idx[(size_t)b * NATOMS + atom];
    ((float4*)x)[i] = ((const float4*)atok)[((size_t)b * NTOK + tok) * 32 + c4];
}

// ---------------- layernorm (standalone, layer-0 ln1 only) -------------------
__global__ void ln_kernel(const float* __restrict__ x, float* __restrict__ out,
                          const float* __restrict__ gw, const float* __restrict__ bw) {
    int row = blockIdx.x * 8 + (threadIdx.x >> 5);
    int lane = threadIdx.x & 31;
    const float4* xr = (const float4*)(x + (size_t)row * 128);
    float4 v = xr[lane];
    float s = v.x + v.y + v.z + v.w;
    float s2 = v.x * v.x + v.y * v.y + v.z * v.z + v.w * v.w;
#pragma unroll
    for (int o = 16; o > 0; o >>= 1) {
        s += __shfl_xor_sync(0xffffffff, s, o);
        s2 += __shfl_xor_sync(0xffffffff, s2, o);
    }
    float mean = s * (1.f / 128.f);
    float var = s2 * (1.f / 128.f) - mean * mean;
    float rs = rsqrtf(var + 1e-5f);
    float4 gg = ((const float4*)gw)[lane];
    float4 bb = ((const float4*)bw)[lane];
    float4 o4;
    o4.x = (v.x - mean) * rs * gg.x + bb.x;
    o4.y = (v.y - mean) * rs * gg.y + bb.y;
    o4.z = (v.z - mean) * rs * gg.z + bb.z;
    o4.w = (v.w - mean) * rs * gg.w + bb.w;
    ((float4*)(out + (size_t)row * 128))[lane] = o4;
}

// ---------------- pair embedding + bias (fused, one block per batch) ---------
__global__ void __launch_bounds__(512)
pairbias_kernel(const float* __restrict__ x,
                const float* __restrict__ Wcl, const float* __restrict__ Wcm,
                const float* __restrict__ Wm1, const float* __restrict__ Wm2,
                const float* __restrict__ Wpb, float* __restrict__ bias) {
    int b = blockIdx.x;
    int t = threadIdx.x;
    __shared__ float Wsum[128][17];
    __shared__ float m1[16][16], m2[16][16];
    __shared__ float t0s[128][17], t1s[128][17];
    __shared__ float p_s[128][17];
    __shared__ float pb[16][4];
    for (int e = t; e < 128 * 16; e += 512) Wsum[e >> 4][e & 15] = Wcl[e] + Wcm[e];
    if (t < 256) m1[t >> 4][t & 15] = Wm1[t];
    else if (t < 512) m2[(t - 256) >> 4][(t - 256) & 15] = Wm2[t - 256];
    if (t >= 448 && t < 512) pb[(t - 448) >> 2][(t - 448) & 3] = Wpb[t - 448];
    __syncthreads();
    int atom = t >> 2, cg = (t & 3) * 4;
    const float4* xr = (const float4*)(x + ((size_t)b * NATOMS + atom) * 128);
    float s[4] = {0.f, 0.f, 0.f, 0.f};
    for (int k4 = 0; k4 < 32; k4++) {
        float4 xv = xr[k4];
#pragma unroll
        for (int c = 0; c < 4; c++) {
            s[c] += xv.x * Wsum[k4 * 4 + 0][cg + c];
            s[c] += xv.y * Wsum[k4 * 4 + 1][cg + c];
            s[c] += xv.z * Wsum[k4 * 4 + 2][cg + c];
            s[c] += xv.w * Wsum[k4 * 4 + 3][cg + c];
        }
    }
#pragma unroll
    for (int c = 0; c < 4; c++) t0s[atom][cg + c] = s[c];
    __syncthreads();
    float s2[4] = {0.f, 0.f, 0.f, 0.f};
#pragma unroll
    for (int k = 0; k < 16; k++) {
        float r = fmaxf(t0s[atom][k], 0.f);
#pragma unroll
        for (int c = 0; c < 4; c++) s2[c] += r * m1[k][cg + c];
    }
#pragma unroll
    for (int c = 0; c < 4; c++) t1s[atom][cg + c] = s2[c];
    __syncthreads();
    float s3[4] = {0.f, 0.f, 0.f, 0.f};
#pragma unroll
    for (int k = 0; k < 16; k++) {
        float r = fmaxf(t1s[atom][k], 0.f);
#pragma unroll
        for (int c = 0; c < 4; c++) s3[c] += r * m2[k][cg + c];
    }
#pragma unroll
    for (int c = 0; c < 4; c++) p_s[atom][cg + c] = s3[c];
    __syncthreads();
#pragma unroll
    for (int u = 0; u < 32; u++) {
        int e = t + 512 * u;
        int h = e >> 12;
        int qk = e & 4095;
        int qi = qk >> 7, j = qk & 127;
        float s = 0.f;
#pragma unroll
        for (int c = 0; c < 16; c++) s += (p_s[qi][c] + p_s[j][c]) * pb[c][h];
        bias[(size_t)b * 16384 + e] = s;
    }
}

// ---------------- windowed attention: block per (b, w, head) -----------------
// V prefetched to registers during score phase; float4 prob reads in AV.
__global__ void __launch_bounds__(128)
attn_kernel(const float* __restrict__ qkv, const float* __restrict__ bias,
            float* __restrict__ o) {
    int bwh = blockIdx.x;
    int h = bwh & 3;
    int w = (bwh >> 2) & (NWIN - 1);
    int b = bwh >> 11;
    int tid = threadIdx.x;
    int wi = tid >> 5, lane = tid & 31;
    __shared__ float q_s[32][36];
    __shared__ float kv_s[128][36];
    __shared__ float sc[32][132];
    const float scale = 0.17677669529663687f;
    size_t base = (size_t)b * NATOMS * 384;
    size_t obase = (size_t)b * NATOMS * 128;
    int a0 = w * 32 - PAD;

    // load Q + K into smem
#pragma unroll
    for (int i = 0; i < 2; i++) {
        int e = tid + 128 * i;
        int r = e >> 3, c4 = e & 7;
        float4 v = *(const float4*)(qkv + base + (size_t)(w * 32 + r) * 384 + h * 32 + c4 * 4);
        *(float4*)(&q_s[r][c4 * 4]) = v;
    }
#pragma unroll
    for (int i = 0; i < 8; i++) {
        int e = tid + 128 * i;
        int r = e >> 3, c4 = e & 7;
        int a = a0 + r;
        float4 v = make_float4(0.f, 0.f, 0.f, 0.f);
        if (a >= 0 && a < NATOMS)
            v = *(const float4*)(qkv + base + (size_t)a * 384 + 128 + h * 32 + c4 * 4);
        *(float4*)(&kv_s[r][c4 * 4]) = v;
    }
    __syncthreads();

    // prefetch V into registers (global latency hidden behind score compute)
    float4 rv[8];
#pragma unroll
    for (int i = 0; i < 8; i++) {
        int e = tid + 128 * i;
        int r = e >> 3, c4 = e & 7;
        int a = a0 + r;
        rv[i] = make_float4(0.f, 0.f, 0.f, 0.f);
        if (a >= 0 && a < NATOMS)
            rv[i] = *(const float4*)(qkv + base + (size_t)a * 384 + 256 + h * 32 + c4 * 4);
    }

    // scores + softmax (fused), q row hoisted
    const float* bb = bias + (((size_t)b * NHEADS + h) * 32) * 128;
#pragma unroll
    for (int rr = 0; rr < 8; rr++) {
        int r = wi * 8 + rr;
        float4 qf[8];
        const float4* qrow = (const float4*)q_s[r];
#pragma unroll
        for (int d4 = 0; d4 < 8; d4++) qf[d4] = qrow[d4];
        float s[4];
#pragma unroll
        for (int c = 0; c < 4; c++) {
            int j = lane + 32 * c;
            float acc = 0.f;
            const float4* krow = (const float4*)kv_s[j];
#pragma unroll
            for (int d4 = 0; d4 < 8; d4++) {
                float4 kk = krow[d4];
                acc += qf[d4].x * kk.x + qf[d4].y * kk.y + qf[d4].z * kk.z + qf[d4].w * kk.w;
            }
            int a = a0 + j;
            s[c] = acc * scale + bb[r * 128 + j];
            if (a < 0 || a >= NATOMS) s[c] = -1e9f;
        }
        float m = fmaxf(fmaxf(s[0], s[1]), fmaxf(s[2], s[3]));
#pragma unroll
        for (int off = 16; off > 0; off >>= 1)
            m = fmaxf(m, __shfl_xor_sync(0xffffffff, m, off));
        float sum = 0.f;
#pragma unroll
        for (int c = 0; c < 4; c++) {
            s[c] = __expf(s[c] - m);
            sum += s[c];
        }
#pragma unroll
        for (int off = 16; off > 0; off >>= 1)
            sum += __shfl_xor_sync(0xffffffff, sum, off);
        float inv = 1.f / sum;
#pragma unroll
        for (int c = 0; c < 4; c++) sc[r][lane + 32 * c] = s[c] * inv;
    }
    __syncthreads();   // all K reads done

    // write prefetched V to smem (aliasing K buffer)
#pragma unroll
    for (int i = 0; i < 8; i++) {
        int e = tid + 128 * i;
        int r = e >> 3, c4 = e & 7;
        *(float4*)(&kv_s[r][c4 * 4]) = rv[i];
    }
    __syncthreads();

    // AV with vectorized prob reads
    {
        int r = tid >> 2, dg = tid & 3;
        float4 acc0 = make_float4(0.f, 0.f, 0.f, 0.f);
        float4 acc1 = make_float4(0.f, 0.f, 0.f, 0.f);
        for (int j4 = 0; j4 < 32; j4++) {
            float4 p4 = *(const float4*)&sc[r][j4 * 4];
            const float* pv = &p4.x;
#pragma unroll
            for (int u = 0; u < 4; u++) {
                float p = pv[u];
                const float4* vrow = (const float4*)kv_s[j4 * 4 + u];
                float4 v0 = vrow[dg * 2];
                float4 v1 = vrow[dg * 2 + 1];
                acc0.x += p * v0.x; acc0.y += p * v0.y;
                acc0.z += p * v0.z; acc0.w += p * v0.w;
                acc1.x += p * v1.x; acc1.y += p * v1.y;
                acc1.z += p * v1.z; acc1.w += p * v1.w;
            }
        }
        float* op = o + obase + (size_t)(w * 32 + r) * 128 + h * 32 + dg * 8;
        *(float4*)op = acc0;
        *(float4*)(op + 4) = acc1;
    }
}

// ---------------- host orchestration -----------------------------------------
extern "C" void kernel_launch(void* const* d_in, const int* in_sizes, int n_in,
                              void* d_out, int out_size) {
    const float* a     = (const float*)d_in[0];
    const int*   idx   = (const int*)d_in[2];
    const float* W_a   = (const float*)d_in[3];
    const float* W_out = (const float*)d_in[4];
    const float* W_cl  = (const float*)d_in[5];
    const float* W_cm  = (const float*)d_in[6];
    const float* Wm1   = (const float*)d_in[7];
    const float* Wm2   = (const float*)d_in[8];
    const float* W_pb  = (const float*)d_in[9];
    const float* Wq    = (const float*)d_in[10];
    const float* Wk    = (const float*)d_in[11];
    const float* Wv    = (const float*)d_in[12];
    const float* Wo    = (const float*)d_in[13];
    const float* ln1g  = (const float*)d_in[14];
    const float* ln1b  = (const float*)d_in[15];
    const float* Wt1   = (const float*)d_in[16];
    const float* Wt2   = (const float*)d_in[17];
    const float* ln2g  = (const float*)d_in[18];
    const float* ln2b  = (const float*)d_in[19];
    float* out = (float*)d_out;

    float *x, *h, *qkv, *o, *hid, *atok, *bias;
    cudaGetSymbolAddress((void**)&x, g_x);
    cudaGetSymbolAddress((void**)&h, g_h);
    cudaGetSymbolAddress((void**)&qkv, g_qkv);
    cudaGetSymbolAddress((void**)&o, g_o);
    cudaGetSymbolAddress((void**)&hid, g_hid);
    cudaGetSymbolAddress((void**)&atok, g_atok);
    cudaGetSymbolAddress((void**)&bias, g_bias);

    unsigned *wqkv_h, *wqkv_l, *wo_h, *wo_l, *wt1_h, *wt1_l, *wt2_h, *wt2_l;
    unsigned *wa_h, *wa_l, *wout_h, *wout_l;
    cudaGetSymbolAddress((void**)&wqkv_h, g_wqkv_h);
    cudaGetSymbolAddress((void**)&wqkv_l, g_wqkv_l);
    cudaGetSymbolAddress((void**)&wo_h, g_wo_h);
    cudaGetSymbolAddress((void**)&wo_l, g_wo_l);
    cudaGetSymbolAddress((void**)&wt1_h, g_wt1_h);
    cudaGetSymbolAddress((void**)&wt1_l, g_wt1_l);
    cudaGetSymbolAddress((void**)&wt2_h, g_wt2_h);
    cudaGetSymbolAddress((void**)&wt2_l, g_wt2_l);
    cudaGetSymbolAddress((void**)&wa_h, g_wa_h);
    cudaGetSymbolAddress((void**)&wa_l, g_wa_l);
    cudaGetSymbolAddress((void**)&wout_h, g_wout_h);
    cudaGetSymbolAddress((void**)&wout_l, g_wout_l);

    const int Mrows = NB * NATOMS;  // 65536

    pack_all<<<S5 / 256, 256>>>(Wq, Wk, Wv, Wo, Wt1, Wt2, W_a, W_out,
                                wqkv_h, wqkv_l, wo_h, wo_l, wt1_h, wt1_l,
                                wt2_h, wt2_l, wa_h, wa_l, wout_h, wout_l);

    gemm_bf3p<128, 64><<<dim3(2, (NB * NTOK) / 128), 256>>>(a, wa_h, wa_l, nullptr, atok,
                                                            NB * NTOK, CATOM, CTOK, 0,
                                                            nullptr, nullptr, nullptr);
    {
        size_t tot = (size_t)NB * NATOMS * 32;
        gather_kernel<<<(unsigned)((tot + 255) / 256), 256>>>(atok, idx, x);
    }

    pairbias_kernel<<<NB, 512>>>(x, W_cl, W_cm, Wm1, Wm2, W_pb, bias);

    ln_kernel<<<Mrows / 8, 256>>>(x, h, ln1g, ln1b);

    for (int l = 0; l < 3; l++) {
        gemm_bf3p<128, 64><<<dim3(6, Mrows / 128), 256>>>(h, wqkv_h + (size_t)l * 384 * 64,
                                                          wqkv_l + (size_t)l * 384 * 64,
                                                          nullptr, qkv, Mrows, 384, 128, 0,
                                                          nullptr, nullptr, nullptr);
        attn_kernel<<<NB * NWIN * NHEADS, 128>>>(qkv, bias, o);
        // Wo gemm: residual + fused ln2 -> h  (BM=64, TBN=128, grid.x=1)
        gemm_bf3p<64, 128><<<dim3(1, Mrows / 64), 256>>>(o, wo_h + (size_t)l * 128 * 64,
                                                         wo_l + (size_t)l * 128 * 64,
                                                         x, x, Mrows, 128, 128, 6,
                                                         ln2g + l * 128, ln2b + l * 128, h);
        gemm_bf3p<128, 64><<<dim3(8, Mrows / 128), 256>>>(h, wt1_h + (size_t)l * 512 * 64,
                                                          wt1_l + (size_t)l * 512 * 64,
                                                          nullptr, hid, Mrows, 512, 128, 1,
                                                          nullptr, nullptr, nullptr);
        if (l < 2) {
            gemm_bf3p<64, 128><<<dim3(1, Mrows / 64), 256>>>(hid, wt2_h + (size_t)l * 128 * 256,
                                                             wt2_l + (size_t)l * 128 * 256,
                                                             x, x, Mrows, 128, 512, 6,
                                                             ln1g + (l + 1) * 128,
                                                             ln1b + (l + 1) * 128, h);
        } else {
            gemm_bf3p<128, 64><<<dim3(2, Mrows / 128), 256>>>(hid, wt2_h + (size_t)l * 128 * 256,
                                                              wt2_l + (size_t)l * 128 * 256,
                                                              x, x, Mrows, 128, 512, 2,
                                                              nullptr, nullptr, nullptr);
        }
    }

    gemm_bf3p<128, 64><<<dim3(2, Mrows / 128), 256>>>(x, wout_h, wout_l, nullptr, out,
                                                      Mrows, 128, 128, 0,
                                                      nullptr, nullptr, nullptr);
}

// round 15
// speedup vs baseline: 1.0453x; 1.0453x over previous
#include <cuda_runtime.h>
#include <cuda_bf16.h>
#include <math.h>

#define NB 4
#define NTOK 2048
#define NATOMS 16384
#define CATOM 128
#define CTOK 384
#define NQ 32
#define NKEY 128
#define NHEADS 4
#define NWIN (NATOMS / NQ)   // 512
#define PAD 48

// ---------------- scratch (static device globals; no allocation) -------------
__device__ float g_x[NB * NATOMS * CATOM];
__device__ float g_h[NB * NATOMS * CATOM];
__device__ float g_qkv[NB * NATOMS * 384];
__device__ float g_o[NB * NATOMS * CATOM];
__device__ float g_hid[NB * NATOMS * 512];
__device__ float g_atok[NB * NTOK * CATOM];
__device__ float g_bias[NB * NHEADS * NQ * NKEY];

// packed bf16 hi/lo weight buffers: layout [N][K/2] words per matrix
__device__ unsigned g_wqkv_h[3 * 384 * 64],  g_wqkv_l[3 * 384 * 64];
__device__ unsigned g_wo_h[3 * 128 * 64],    g_wo_l[3 * 128 * 64];
__device__ unsigned g_wt1_h[3 * 512 * 64],   g_wt1_l[3 * 512 * 64];
__device__ unsigned g_wt2_h[3 * 128 * 256],  g_wt2_l[3 * 128 * 256];
__device__ unsigned g_wa_h[128 * 192],       g_wa_l[128 * 192];
__device__ unsigned g_wout_h[128 * 64],      g_wout_l[128 * 64];

// ---------------- helpers ----------------------------------------------------
__device__ __forceinline__ void mma_bf16(float* c, const unsigned* a, const unsigned* b) {
    asm volatile(
        "mma.sync.aligned.m16n8k16.row.col.f32.bf16.bf16.f32 "
        "{%0,%1,%2,%3}, {%4,%5,%6,%7}, {%8,%9}, {%0,%1,%2,%3};"
        : "+f"(c[0]), "+f"(c[1]), "+f"(c[2]), "+f"(c[3])
        : "r"(a[0]), "r"(a[1]), "r"(a[2]), "r"(a[3]), "r"(b[0]), "r"(b[1]));
}
__device__ __forceinline__ void ldsm_x4(unsigned& r0, unsigned& r1, unsigned& r2,
                                        unsigned& r3, unsigned addr) {
    asm volatile("ldmatrix.sync.aligned.m8n8.x4.shared.b16 {%0,%1,%2,%3}, [%4];"
                 : "=r"(r0), "=r"(r1), "=r"(r2), "=r"(r3) : "r"(addr));
}
__device__ __forceinline__ void pack2(float f0, float f1, unsigned& hi, unsigned& lo) {
    unsigned short h0 = __bfloat16_as_ushort(__float2bfloat16(f0));
    unsigned short h1 = __bfloat16_as_ushort(__float2bfloat16(f1));
    float r0 = f0 - __bfloat162float(__ushort_as_bfloat16(h0));
    float r1 = f1 - __bfloat162float(__ushort_as_bfloat16(h1));
    unsigned short l0 = __bfloat16_as_ushort(__float2bfloat16(r0));
    unsigned short l1 = __bfloat16_as_ushort(__float2bfloat16(r1));
    hi = (unsigned)h0 | ((unsigned)h1 << 16);
    lo = (unsigned)l0 | ((unsigned)l1 << 16);
}
__device__ __forceinline__ void pack_w_elem(const float* W, int K, int N, int e,
                                            unsigned* hi, unsigned* lo) {
    int Kw = K >> 1;
    int m = e / (N * Kw);
    int rem = e - m * N * Kw;
    int n = rem / Kw, kw = rem - n * Kw;
    const float* Wm = W + (size_t)m * K * N;
    pack2(Wm[(size_t)(2 * kw) * N + n], Wm[(size_t)(2 * kw + 1) * N + n], hi[e], lo[e]);
}

// ---------------- single weight-pack kernel ----------------------------------
#define S0 73728
#define S1 (S0 + 24576)
#define S2 (S1 + 98304)
#define S3 (S2 + 98304)
#define S4 (S3 + 24576)
#define S5 (S4 + 8192)
__global__ void pack_all(const float* __restrict__ Wq, const float* __restrict__ Wk,
                         const float* __restrict__ Wv, const float* __restrict__ Wo,
                         const float* __restrict__ Wt1, const float* __restrict__ Wt2,
                         const float* __restrict__ W_a, const float* __restrict__ W_out,
                         unsigned* qkv_h, unsigned* qkv_l, unsigned* wo_h, unsigned* wo_l,
                         unsigned* wt1_h, unsigned* wt1_l, unsigned* wt2_h, unsigned* wt2_l,
                         unsigned* wa_h, unsigned* wa_l, unsigned* wout_h, unsigned* wout_l) {
    int e = blockIdx.x * blockDim.x + threadIdx.x;
    if (e < S0) {
        int l = e / (384 * 64);
        int rem = e - l * (384 * 64);
        int n = rem >> 6, kw = rem & 63;
        const float* src = ((n < 128) ? Wq : (n < 256) ? Wk : Wv) + (size_t)l * 128 * 128;
        int nn = n & 127;
        pack2(src[(size_t)(2 * kw) * 128 + nn], src[(size_t)(2 * kw + 1) * 128 + nn],
              qkv_h[e], qkv_l[e]);
    } else if (e < S1) pack_w_elem(Wo, 128, 128, e - S0, wo_h, wo_l);
    else if (e < S2) pack_w_elem(Wt1, 128, 512, e - S1, wt1_h, wt1_l);
    else if (e < S3) pack_w_elem(Wt2, 512, 128, e - S2, wt2_h, wt2_l);
    else if (e < S4) pack_w_elem(W_a, 384, 128, e - S3, wa_h, wa_l);
    else if (e < S5) pack_w_elem(W_out, 128, 128, e - S4, wout_h, wout_l);
}

// ---------------- 3xBF16 GEMM, templated on BM x BN tile ---------------------
// flags: bit0=relu, bit1=add Cin, bit2=fused LN->H (needs TBN=128, grid.x=1, Cin)
template <int TBM, int TBN>
__global__ void __launch_bounds__(256)
gemm_bf3p(const float* __restrict__ A, const unsigned* __restrict__ Bhi,
          const unsigned* __restrict__ Blo, const float* __restrict__ Cin,
          float* __restrict__ C, int M, int N, int K, int flags,
          const float* __restrict__ LNg, const float* __restrict__ LNb,
          float* __restrict__ H) {
    constexpr int NWN = TBN / 32;          // warps along n
    constexpr int NWM = 8 / NWN;           // warps along m
    constexpr int MI = TBM / (16 * NWM);   // 16-row m-tiles per warp
    constexpr int TPRA = 256 / TBM;        // threads per A row
    constexpr int AWPT = 16 / TPRA;        // packed words per thread (A)
    __shared__ unsigned Ah[TBM][20], Al[TBM][20];
    __shared__ unsigned Bh[TBN][20], Bl[TBN][20];
    int tid = threadIdx.x;
    int wid = tid >> 5, lane = tid & 31;
    int wm = wid / NWN, wn = wid % NWN;
    int g = lane >> 2, tg = lane & 3;
    const float* Ag = A + (size_t)blockIdx.y * TBM * K;
    int Kw = K >> 1;
    const unsigned* Bgh = Bhi + (size_t)blockIdx.x * TBN * Kw;
    const unsigned* Bgl = Blo + (size_t)blockIdx.x * TBN * Kw;
    float c[MI][4][4] = {};

    int lrow = lane & 15;
    int lph = (lane >> 4) * 4;
    unsigned aHb = (unsigned)__cvta_generic_to_shared(&Ah[0][0]);
    unsigned aLb = (unsigned)__cvta_generic_to_shared(&Al[0][0]);
    unsigned bHb = (unsigned)__cvta_generic_to_shared(&Bh[0][0]);
    unsigned bLb = (unsigned)__cvta_generic_to_shared(&Bl[0][0]);

    int arow = tid / TPRA, aw = (tid % TPRA) * AWPT;
    int brow, bwd;
    if (TBN == 128) { brow = tid >> 1; bwd = (tid & 1) * 8; }
    else            { brow = tid >> 2; bwd = (tid & 3) * 4; }
    float4 ra[AWPT / 2];
    uint4 rbh0, rbh1, rbl0, rbl1;

#pragma unroll
    for (int i = 0; i < AWPT / 2; i++)
        ra[i] = *(const float4*)(Ag + (size_t)arow * K + aw * 2 + 4 * i);
    rbh0 = *(const uint4*)(Bgh + (size_t)brow * Kw + bwd);
    rbl0 = *(const uint4*)(Bgl + (size_t)brow * Kw + bwd);
    if (TBN == 128) {
        rbh1 = *(const uint4*)(Bgh + (size_t)brow * Kw + bwd + 4);
        rbl1 = *(const uint4*)(Bgl + (size_t)brow * Kw + bwd + 4);
    }

    int tiles = K / 32;
    for (int t = 0; t < tiles; t++) {
        {
            unsigned wh[AWPT], wl[AWPT];
#pragma unroll
            for (int i = 0; i < AWPT / 2; i++) {
                pack2(ra[i].x, ra[i].y, wh[2 * i], wl[2 * i]);
                pack2(ra[i].z, ra[i].w, wh[2 * i + 1], wl[2 * i + 1]);
            }
#pragma unroll
            for (int u = 0; u < AWPT / 4; u++) {
                *(uint4*)&Ah[arow][aw + 4 * u] =
                    make_uint4(wh[4 * u], wh[4 * u + 1], wh[4 * u + 2], wh[4 * u + 3]);
                *(uint4*)&Al[arow][aw + 4 * u] =
                    make_uint4(wl[4 * u], wl[4 * u + 1], wl[4 * u + 2], wl[4 * u + 3]);
            }
            *(uint4*)&Bh[brow][bwd] = rbh0;
            *(uint4*)&Bl[brow][bwd] = rbl0;
            if (TBN == 128) {
                *(uint4*)&Bh[brow][bwd + 4] = rbh1;
                *(uint4*)&Bl[brow][bwd + 4] = rbl1;
            }
        }
        __syncthreads();
        if (t + 1 < tiles) {
            int kt = (t + 1) * 32;
#pragma unroll
            for (int i = 0; i < AWPT / 2; i++)
                ra[i] = *(const float4*)(Ag + (size_t)arow * K + kt + aw * 2 + 4 * i);
            int ktw = kt >> 1;
            rbh0 = *(const uint4*)(Bgh + (size_t)brow * Kw + ktw + bwd);
            rbl0 = *(const uint4*)(Bgl + (size_t)brow * Kw + ktw + bwd);
            if (TBN == 128) {
                rbh1 = *(const uint4*)(Bgh + (size_t)brow * Kw + ktw + bwd + 4);
                rbl1 = *(const uint4*)(Bgl + (size_t)brow * Kw + ktw + bwd + 4);
            }
        }
#pragma unroll
        for (int ks2 = 0; ks2 < 2; ks2++) {
            int kc = ks2 * 8 + lph;
            unsigned ah[MI][4], al[MI][4], bhf[2][4], blf[2][4];
#pragma unroll
            for (int i = 0; i < MI; i++) {
                unsigned off = (unsigned)(((wm * 16 * MI + i * 16 + lrow) * 20 + kc) * 4);
                ldsm_x4(ah[i][0], ah[i][1], ah[i][2], ah[i][3], aHb + off);
                ldsm_x4(al[i][0], al[i][1], al[i][2], al[i][3], aLb + off);
            }
#pragma unroll
            for (int jp = 0; jp < 2; jp++) {
                unsigned off = (unsigned)(((wn * 32 + jp * 16 + lrow) * 20 + kc) * 4);
                ldsm_x4(bhf[jp][0], bhf[jp][1], bhf[jp][2], bhf[jp][3], bHb + off);
                ldsm_x4(blf[jp][0], blf[jp][1], blf[jp][2], blf[jp][3], bLb + off);
            }
#pragma unroll
            for (int i = 0; i < MI; i++)
#pragma unroll
                for (int j = 0; j < 4; j++) {
                    unsigned bh2[2] = {bhf[j >> 1][j & 1], bhf[j >> 1][(j & 1) + 2]};
                    unsigned bl2[2] = {blf[j >> 1][j & 1], blf[j >> 1][(j & 1) + 2]};
                    mma_bf16(c[i][j], ah[i], bl2);
                    mma_bf16(c[i][j], al[i], bh2);
                    mma_bf16(c[i][j], ah[i], bh2);
                }
        }
        __syncthreads();
    }

    if (TBN == 128) {
        if (flags & 4) {
            float* rsum = (float*)&Ah[0][0];    // [TBM][4]
            float* rsq  = (float*)&Al[0][0];
            float* gln  = (float*)&Bh[0][0];
            float* bln  = gln + 128;
            if (tid < 128) gln[tid] = LNg[tid];
            else if (tid < 256) bln[tid - 128] = LNb[tid - 128];
#pragma unroll
            for (int i = 0; i < MI; i++) {
#pragma unroll
                for (int hf = 0; hf < 2; hf++) {
                    int r = wm * 16 * MI + i * 16 + g + hf * 8;
                    float ps = 0.f, pq = 0.f;
#pragma unroll
                    for (int j = 0; j < 4; j++) {
                        int tt = hf * 2;
                        size_t idx = (size_t)(blockIdx.y * TBM + r) * 128 + wn * 32 + j * 8 + 2 * tg;
                        float2 p = *(const float2*)(Cin + idx);
                        float v0 = c[i][j][tt] + p.x;
                        float v1 = c[i][j][tt + 1] + p.y;
                        c[i][j][tt] = v0; c[i][j][tt + 1] = v1;
                        ps += v0 + v1; pq += v0 * v0 + v1 * v1;
                    }
                    ps += __shfl_xor_sync(0xffffffff, ps, 1);
                    ps += __shfl_xor_sync(0xffffffff, ps, 2);
                    pq += __shfl_xor_sync(0xffffffff, pq, 1);
                    pq += __shfl_xor_sync(0xffffffff, pq, 2);
                    if (tg == 0) { rsum[r * 4 + wn] = ps; rsq[r * 4 + wn] = pq; }
                }
            }
            __syncthreads();
#pragma unroll
            for (int i = 0; i < MI; i++) {
#pragma unroll
                for (int hf = 0; hf < 2; hf++) {
                    int r = wm * 16 * MI + i * 16 + g + hf * 8;
                    float4 s4 = *(float4*)&rsum[r * 4];
                    float4 q4 = *(float4*)&rsq[r * 4];
                    float mean = (s4.x + s4.y + s4.z + s4.w) * (1.f / 128.f);
                    float var = (q4.x + q4.y + q4.z + q4.w) * (1.f / 128.f) - mean * mean;
                    float rstd = rsqrtf(var + 1e-5f);
                    size_t rowoff = (size_t)(blockIdx.y * TBM + r) * 128;
#pragma unroll
                    for (int j = 0; j < 4; j++) {
                        int tt = hf * 2;
                        int col = wn * 32 + j * 8 + 2 * tg;
                        float v0 = c[i][j][tt], v1 = c[i][j][tt + 1];
                        *(float2*)(C + rowoff + col) = make_float2(v0, v1);
                        float h0 = (v0 - mean) * rstd * gln[col] + bln[col];
                        float h1 = (v1 - mean) * rstd * gln[col + 1] + bln[col + 1];
                        *(float2*)(H + rowoff + col) = make_float2(h0, h1);
                    }
                }
            }
            return;
        }
    }

#pragma unroll
    for (int i = 0; i < MI; i++) {
        int r0 = blockIdx.y * TBM + wm * 16 * MI + i * 16 + g;
#pragma unroll
        for (int j = 0; j < 4; j++) {
            int c0 = blockIdx.x * TBN + wn * 32 + j * 8 + 2 * tg;
            float2 v0 = make_float2(c[i][j][0], c[i][j][1]);
            float2 v1 = make_float2(c[i][j][2], c[i][j][3]);
            if (flags & 1) {
                v0.x = fmaxf(v0.x, 0.f); v0.y = fmaxf(v0.y, 0.f);
                v1.x = fmaxf(v1.x, 0.f); v1.y = fmaxf(v1.y, 0.f);
            }
            size_t i0 = (size_t)r0 * N + c0;
            size_t i1 = (size_t)(r0 + 8) * N + c0;
            if (flags & 2) {
                float2 p0 = *(const float2*)(Cin + i0);
                float2 p1 = *(const float2*)(Cin + i1);
                v0.x += p0.x; v0.y += p0.y;
                v1.x += p1.x; v1.y += p1.y;
            }
            *(float2*)(C + i0) = v0;
            *(float2*)(C + i1) = v1;
        }
    }
}

// ---------------- gather token features to atoms (float4) --------------------
__global__ void gather_kernel(const float* __restrict__ atok, const int* __restrict__ idx,
                              float* __restrict__ x) {
    size_t i = (size_t)blockIdx.x * blockDim.x + threadIdx.x;
    if (i >= (size_t)NB * NATOMS * 32) return;
    int c4 = (int)(i & 31);
    size_t n = i >> 5;
    int b = (int)(n >> 14);
    int atom = (int)(n & (NATOMS - 1));
    int tok = idx[(size_t)b * NATOMS + atom];
    ((float4*)x)[i] = ((const float4*)atok)[((size_t)b * NTOK + tok) * 32 + c4];
}

// ---------------- layernorm (standalone, layer-0 ln1 only) -------------------
__global__ void ln_kernel(const float* __restrict__ x, float* __restrict__ out,
                          const float* __restrict__ gw, const float* __restrict__ bw) {
    int row = blockIdx.x * 8 + (threadIdx.x >> 5);
    int lane = threadIdx.x & 31;
    const float4* xr = (const float4*)(x + (size_t)row * 128);
    float4 v = xr[lane];
    float s = v.x + v.y + v.z + v.w;
    float s2 = v.x * v.x + v.y * v.y + v.z * v.z + v.w * v.w;
#pragma unroll
    for (int o = 16; o > 0; o >>= 1) {
        s += __shfl_xor_sync(0xffffffff, s, o);
        s2 += __shfl_xor_sync(0xffffffff, s2, o);
    }
    float mean = s * (1.f / 128.f);
    float var = s2 * (1.f / 128.f) - mean * mean;
    float rs = rsqrtf(var + 1e-5f);
    float4 gg = ((const float4*)gw)[lane];
    float4 bb = ((const float4*)bw)[lane];
    float4 o4;
    o4.x = (v.x - mean) * rs * gg.x + bb.x;
    o4.y = (v.y - mean) * rs * gg.y + bb.y;
    o4.z = (v.z - mean) * rs * gg.z + bb.z;
    o4.w = (v.w - mean) * rs * gg.w + bb.w;
    ((float4*)(out + (size_t)row * 128))[lane] = o4;
}

// ---------------- pair embedding + bias (fused, one block per batch) ---------
__global__ void __launch_bounds__(512)
pairbias_kernel(const float* __restrict__ x,
                const float* __restrict__ Wcl, const float* __restrict__ Wcm,
                const float* __restrict__ Wm1, const float* __restrict__ Wm2,
                const float* __restrict__ Wpb, float* __restrict__ bias) {
    int b = blockIdx.x;
    int t = threadIdx.x;
    __shared__ float Wsum[128][17];
    __shared__ float m1[16][16], m2[16][16];
    __shared__ float t0s[128][17], t1s[128][17];
    __shared__ float p_s[128][17];
    __shared__ float pb[16][4];
    for (int e = t; e < 128 * 16; e += 512) Wsum[e >> 4][e & 15] = Wcl[e] + Wcm[e];
    if (t < 256) m1[t >> 4][t & 15] = Wm1[t];
    else if (t < 512) m2[(t - 256) >> 4][(t - 256) & 15] = Wm2[t - 256];
    if (t >= 448 && t < 512) pb[(t - 448) >> 2][(t - 448) & 3] = Wpb[t - 448];
    __syncthreads();
    int atom = t >> 2, cg = (t & 3) * 4;
    const float4* xr = (const float4*)(x + ((size_t)b * NATOMS + atom) * 128);
    float s[4] = {0.f, 0.f, 0.f, 0.f};
    for (int k4 = 0; k4 < 32; k4++) {
        float4 xv = xr[k4];
#pragma unroll
        for (int c = 0; c < 4; c++) {
            s[c] += xv.x * Wsum[k4 * 4 + 0][cg + c];
            s[c] += xv.y * Wsum[k4 * 4 + 1][cg + c];
            s[c] += xv.z * Wsum[k4 * 4 + 2][cg + c];
            s[c] += xv.w * Wsum[k4 * 4 + 3][cg + c];
        }
    }
#pragma unroll
    for (int c = 0; c < 4; c++) t0s[atom][cg + c] = s[c];
    __syncthreads();
    float s2[4] = {0.f, 0.f, 0.f, 0.f};
#pragma unroll
    for (int k = 0; k < 16; k++) {
        float r = fmaxf(t0s[atom][k], 0.f);
#pragma unroll
        for (int c = 0; c < 4; c++) s2[c] += r * m1[k][cg + c];
    }
#pragma unroll
    for (int c = 0; c < 4; c++) t1s[atom][cg + c] = s2[c];
    __syncthreads();
    float s3[4] = {0.f, 0.f, 0.f, 0.f};
#pragma unroll
    for (int k = 0; k < 16; k++) {
        float r = fmaxf(t1s[atom][k], 0.f);
#pragma unroll
        for (int c = 0; c < 4; c++) s3[c] += r * m2[k][cg + c];
    }
#pragma unroll
    for (int c = 0; c < 4; c++) p_s[atom][cg + c] = s3[c];
    __syncthreads();
#pragma unroll
    for (int u = 0; u < 32; u++) {
        int e = t + 512 * u;
        int h = e >> 12;
        int qk = e & 4095;
        int qi = qk >> 7, j = qk & 127;
        float s = 0.f;
#pragma unroll
        for (int c = 0; c < 16; c++) s += (p_s[qi][c] + p_s[j][c]) * pb[c][h];
        bias[(size_t)b * 16384 + e] = s;
    }
}

// ---------------- windowed attention: block per (b, w, head) -----------------
// R12 structure; only change: sc stride 132 + float4 prob reads in AV.
__global__ void __launch_bounds__(128)
attn_kernel(const float* __restrict__ qkv, const float* __restrict__ bias,
            float* __restrict__ o) {
    int bwh = blockIdx.x;
    int h = bwh & 3;
    int w = (bwh >> 2) & (NWIN - 1);
    int b = bwh >> 11;
    int tid = threadIdx.x;
    int wi = tid >> 5, lane = tid & 31;
    __shared__ float q_s[32][36];
    __shared__ float kv_s[128][36];
    __shared__ float sc[32][132];
    const float scale = 0.17677669529663687f;
    size_t base = (size_t)b * NATOMS * 384;
    size_t obase = (size_t)b * NATOMS * 128;
    int a0 = w * 32 - PAD;

#pragma unroll
    for (int i = 0; i < 2; i++) {
        int e = tid + 128 * i;
        int r = e >> 3, c4 = e & 7;
        float4 v = *(const float4*)(qkv + base + (size_t)(w * 32 + r) * 384 + h * 32 + c4 * 4);
        *(float4*)(&q_s[r][c4 * 4]) = v;
    }
#pragma unroll
    for (int i = 0; i < 8; i++) {
        int e = tid + 128 * i;
        int r = e >> 3, c4 = e & 7;
        int a = a0 + r;
        float4 v = make_float4(0.f, 0.f, 0.f, 0.f);
        if (a >= 0 && a < NATOMS)
            v = *(const float4*)(qkv + base + (size_t)a * 384 + 128 + h * 32 + c4 * 4);
        *(float4*)(&kv_s[r][c4 * 4]) = v;
    }
    __syncthreads();

    const float* bb = bias + (((size_t)b * NHEADS + h) * 32) * 128;
#pragma unroll
    for (int rr = 0; rr < 8; rr++) {
        int r = wi * 8 + rr;
        float s[4];
#pragma unroll
        for (int c = 0; c < 4; c++) {
            int j = lane + 32 * c;
            float acc = 0.f;
            const float4* qrow = (const float4*)q_s[r];
            const float4* krow = (const float4*)kv_s[j];
#pragma unroll
            for (int d4 = 0; d4 < 8; d4++) {
                float4 qq = qrow[d4];
                float4 kk = krow[d4];
                acc += qq.x * kk.x + qq.y * kk.y + qq.z * kk.z + qq.w * kk.w;
            }
            int a = a0 + j;
            s[c] = acc * scale + bb[r * 128 + j];
            if (a < 0 || a >= NATOMS) s[c] = -1e9f;
        }
        float m = fmaxf(fmaxf(s[0], s[1]), fmaxf(s[2], s[3]));
#pragma unroll
        for (int off = 16; off > 0; off >>= 1)
            m = fmaxf(m, __shfl_xor_sync(0xffffffff, m, off));
        float sum = 0.f;
#pragma unroll
        for (int c = 0; c < 4; c++) {
            s[c] = __expf(s[c] - m);
            sum += s[c];
        }
#pragma unroll
        for (int off = 16; off > 0; off >>= 1)
            sum += __shfl_xor_sync(0xffffffff, sum, off);
        float inv = 1.f / sum;
#pragma unroll
        for (int c = 0; c < 4; c++) sc[r][lane + 32 * c] = s[c] * inv;
    }
    __syncthreads();

#pragma unroll
    for (int i = 0; i < 8; i++) {
        int e = tid + 128 * i;
        int r = e >> 3, c4 = e & 7;
        int a = a0 + r;
        float4 v = make_float4(0.f, 0.f, 0.f, 0.f);
        if (a >= 0 && a < NATOMS)
            v = *(const float4*)(qkv + base + (size_t)a * 384 + 256 + h * 32 + c4 * 4);
        *(float4*)(&kv_s[r][c4 * 4]) = v;
    }
    __syncthreads();

    {
        int r = tid >> 2, dg = tid & 3;
        float4 acc0 = make_float4(0.f, 0.f, 0.f, 0.f);
        float4 acc1 = make_float4(0.f, 0.f, 0.f, 0.f);
        for (int j4 = 0; j4 < 32; j4++) {
            float4 p4 = *(const float4*)&sc[r][j4 * 4];
            const float* pv = &p4.x;
#pragma unroll
            for (int u = 0; u < 4; u++) {
                float p = pv[u];
                const float4* vrow = (const float4*)kv_s[j4 * 4 + u];
                float4 v0 = vrow[dg * 2];
                float4 v1 = vrow[dg * 2 + 1];
                acc0.x += p * v0.x; acc0.y += p * v0.y;
                acc0.z += p * v0.z; acc0.w += p * v0.w;
                acc1.x += p * v1.x; acc1.y += p * v1.y;
                acc1.z += p * v1.z; acc1.w += p * v1.w;
            }
        }
        float* op = o + obase + (size_t)(w * 32 + r) * 128 + h * 32 + dg * 8;
        *(float4*)op = acc0;
        *(float4*)(op + 4) = acc1;
    }
}

// ---------------- host orchestration -----------------------------------------
extern "C" void kernel_launch(void* const* d_in, const int* in_sizes, int n_in,
                              void* d_out, int out_size) {
    const float* a     = (const float*)d_in[0];
    const int*   idx   = (const int*)d_in[2];
    const float* W_a   = (const float*)d_in[3];
    const float* W_out = (const float*)d_in[4];
    const float* W_cl  = (const float*)d_in[5];
    const float* W_cm  = (const float*)d_in[6];
    const float* Wm1   = (const float*)d_in[7];
    const float* Wm2   = (const float*)d_in[8];
    const float* W_pb  = (const float*)d_in[9];
    const float* Wq    = (const float*)d_in[10];
    const float* Wk    = (const float*)d_in[11];
    const float* Wv    = (const float*)d_in[12];
    const float* Wo    = (const float*)d_in[13];
    const float* ln1g  = (const float*)d_in[14];
    const float* ln1b  = (const float*)d_in[15];
    const float* Wt1   = (const float*)d_in[16];
    const float* Wt2   = (const float*)d_in[17];
    const float* ln2g  = (const float*)d_in[18];
    const float* ln2b  = (const float*)d_in[19];
    float* out = (float*)d_out;

    float *x, *h, *qkv, *o, *hid, *atok, *bias;
    cudaGetSymbolAddress((void**)&x, g_x);
    cudaGetSymbolAddress((void**)&h, g_h);
    cudaGetSymbolAddress((void**)&qkv, g_qkv);
    cudaGetSymbolAddress((void**)&o, g_o);
    cudaGetSymbolAddress((void**)&hid, g_hid);
    cudaGetSymbolAddress((void**)&atok, g_atok);
    cudaGetSymbolAddress((void**)&bias, g_bias);

    unsigned *wqkv_h, *wqkv_l, *wo_h, *wo_l, *wt1_h, *wt1_l, *wt2_h, *wt2_l;
    unsigned *wa_h, *wa_l, *wout_h, *wout_l;
    cudaGetSymbolAddress((void**)&wqkv_h, g_wqkv_h);
    cudaGetSymbolAddress((void**)&wqkv_l, g_wqkv_l);
    cudaGetSymbolAddress((void**)&wo_h, g_wo_h);
    cudaGetSymbolAddress((void**)&wo_l, g_wo_l);
    cudaGetSymbolAddress((void**)&wt1_h, g_wt1_h);
    cudaGetSymbolAddress((void**)&wt1_l, g_wt1_l);
    cudaGetSymbolAddress((void**)&wt2_h, g_wt2_h);
    cudaGetSymbolAddress((void**)&wt2_l, g_wt2_l);
    cudaGetSymbolAddress((void**)&wa_h, g_wa_h);
    cudaGetSymbolAddress((void**)&wa_l, g_wa_l);
    cudaGetSymbolAddress((void**)&wout_h, g_wout_h);
    cudaGetSymbolAddress((void**)&wout_l, g_wout_l);

    const int Mrows = NB * NATOMS;  // 65536

    pack_all<<<S5 / 256, 256>>>(Wq, Wk, Wv, Wo, Wt1, Wt2, W_a, W_out,
                                wqkv_h, wqkv_l, wo_h, wo_l, wt1_h, wt1_l,
                                wt2_h, wt2_l, wa_h, wa_l, wout_h, wout_l);

    gemm_bf3p<128, 64><<<dim3(2, (NB * NTOK) / 128), 256>>>(a, wa_h, wa_l, nullptr, atok,
                                                            NB * NTOK, CATOM, CTOK, 0,
                                                            nullptr, nullptr, nullptr);
    {
        size_t tot = (size_t)NB * NATOMS * 32;
        gather_kernel<<<(unsigned)((tot + 255) / 256), 256>>>(atok, idx, x);
    }

    pairbias_kernel<<<NB, 512>>>(x, W_cl, W_cm, Wm1, Wm2, W_pb, bias);

    ln_kernel<<<Mrows / 8, 256>>>(x, h, ln1g, ln1b);

    for (int l = 0; l < 3; l++) {
        gemm_bf3p<128, 64><<<dim3(6, Mrows / 128), 256>>>(h, wqkv_h + (size_t)l * 384 * 64,
                                                          wqkv_l + (size_t)l * 384 * 64,
                                                          nullptr, qkv, Mrows, 384, 128, 0,
                                                          nullptr, nullptr, nullptr);
        attn_kernel<<<NB * NWIN * NHEADS, 128>>>(qkv, bias, o);
        // Wo gemm: residual + fused ln2 -> h  (BM=64, TBN=128, grid.x=1)
        gemm_bf3p<64, 128><<<dim3(1, Mrows / 64), 256>>>(o, wo_h + (size_t)l * 128 * 64,
                                                         wo_l + (size_t)l * 128 * 64,
                                                         x, x, Mrows, 128, 128, 6,
                                                         ln2g + l * 128, ln2b + l * 128, h);
        gemm_bf3p<128, 64><<<dim3(8, Mrows / 128), 256>>>(h, wt1_h + (size_t)l * 512 * 64,
                                                          wt1_l + (size_t)l * 512 * 64,
                                                          nullptr, hid, Mrows, 512, 128, 1,
                                                          nullptr, nullptr, nullptr);
        if (l < 2) {
            gemm_bf3p<64, 128><<<dim3(1, Mrows / 64), 256>>>(hid, wt2_h + (size_t)l * 128 * 256,
                                                             wt2_l + (size_t)l * 128 * 256,
                                                             x, x, Mrows, 128, 512, 6,
                                                             ln1g + (l + 1) * 128,
                                                             ln1b + (l + 1) * 128, h);
        } else {
            gemm_bf3p<128, 64><<<dim3(2, Mrows / 128), 256>>>(hid, wt2_h + (size_t)l * 128 * 256,
                                                              wt2_l + (size_t)l * 128 * 256,
                                                              x, x, Mrows, 128, 512, 2,
                                                              nullptr, nullptr, nullptr);
        }
    }

    gemm_bf3p<128, 64><<<dim3(2, Mrows / 128), 256>>>(x, wout_h, wout_l, nullptr, out,
                                                      Mrows, 128, 128, 0,
                                                      nullptr, nullptr, nullptr);
}